// round 9
// baseline (speedup 1.0000x reference)
#include <cuda_runtime.h>
#include <cstdint>

#define NNODES 100000
#define NEDGES 1600000
#define FDIM   64
#define KCHEB  6
#define NF     (NNODES * FDIM)

// ---------------- scratch (device globals) ----------------------------------
__device__ int   g_degi[NNODES];
__device__ float g_dis[NNODES];
__device__ int   g_rowptr[NNODES + 1];
__device__ int   g_cursor[NNODES];
__device__ unsigned long long g_edge[NEDGES];   // packed (w<<32 | col)
__device__ float g_T[5][NF];                    // T1..T5 (T0 = x input)

// ---------------- helpers ----------------------------------------------------
__device__ __forceinline__ float2 unpack2(unsigned long long u) {
    float2 v;
    asm("mov.b64 {%0, %1}, %2;" : "=f"(v.x), "=f"(v.y) : "l"(u));
    return v;
}
__device__ __forceinline__ void fma2(unsigned long long &acc, float t, unsigned long long w) {
    unsigned long long tt;
    asm("mov.b64 %0, {%1, %1};" : "=l"(tt) : "f"(t));
    asm("fma.rn.f32x2 %0, %1, %2, %0;" : "+l"(acc) : "l"(tt), "l"(w));
}

// ---------------- 1. degree count (int) --------------------------------------
__global__ void k_count(const int* __restrict__ ei) {
    int e = blockIdx.x * blockDim.x + threadIdx.x;
    if (e >= NEDGES) return;
    atomicAdd(&g_degi[ei[e]], 1);
}

// ---------------- 2. scan -> rowptr, plus D^{-1/2} (fused) --------------------
__global__ void __launch_bounds__(1024, 1) k_scan() {
    __shared__ int warpsum[32];
    int t = threadIdx.x;
    const int CH = (NNODES + 1023) / 1024;
    int base = t * CH;
    int sum = 0;
    for (int j = 0; j < CH; j++) {
        int i = base + j;
        if (i < NNODES) sum += g_degi[i];
    }
    int lane = t & 31, w = t >> 5;
    int v = sum;
    #pragma unroll
    for (int off = 1; off < 32; off <<= 1) {
        int u = __shfl_up_sync(0xffffffffu, v, off);
        if (lane >= off) v += u;
    }
    if (lane == 31) warpsum[w] = v;
    __syncthreads();
    if (w == 0) {
        int s = warpsum[lane];
        #pragma unroll
        for (int off = 1; off < 32; off <<= 1) {
            int u = __shfl_up_sync(0xffffffffu, s, off);
            if (lane >= off) s += u;
        }
        warpsum[lane] = s;
    }
    __syncthreads();
    int off = (v - sum) + (w ? warpsum[w - 1] : 0);   // exclusive prefix
    for (int j = 0; j < CH; j++) {
        int i = base + j;
        if (i < NNODES) {
            int d = g_degi[i];
            g_rowptr[i] = off;
            g_cursor[i] = 0;
            g_dis[i] = (d > 0) ? rsqrtf((float)d) : 0.0f;
            off += d;
        }
    }
    if (t == 1023) g_rowptr[NNODES] = NEDGES;
}

// ---------------- 3. fill CSR records (col, w) --------------------------------
__global__ void k_fill(const int* __restrict__ ei) {
    int e = blockIdx.x * blockDim.x + threadIdx.x;
    if (e >= NEDGES) return;
    int r = ei[e];
    int c = ei[NEDGES + e];
    float w = -g_dis[r] * g_dis[c];
    int pos = atomicAdd(&g_cursor[r], 1);
    unsigned long long rec = ((unsigned long long)__float_as_uint(w) << 32) | (unsigned)c;
    g_edge[g_rowptr[r] + pos] = rec;
}

// ---------------- 4. gather prop: dst[n] = scale*sum_e w*src[col] - prev[n] ---
// 16 lanes per node (float4 per lane), 2 nodes per warp, 8-deep batch.
__global__ void __launch_bounds__(256)
k_gather(const float* __restrict__ src, const float* __restrict__ prev,
         float* __restrict__ dst, float scale) {
    int gid = blockIdx.x * blockDim.x + threadIdx.x;
    int node = gid >> 4;
    if (node >= NNODES) return;
    int lane = gid & 15;
    int i = g_rowptr[node], end = g_rowptr[node + 1];
    float4 acc = make_float4(0.0f, 0.0f, 0.0f, 0.0f);

    for (; i + 8 <= end; i += 8) {
        unsigned long long r[8];
        #pragma unroll
        for (int u = 0; u < 8; u++) r[u] = g_edge[i + u];
        float4 v[8];
        #pragma unroll
        for (int u = 0; u < 8; u++)
            v[u] = ((const float4*)(src + (size_t)(unsigned)r[u] * FDIM))[lane];
        #pragma unroll
        for (int u = 0; u < 8; u++) {
            float w = __uint_as_float((unsigned)(r[u] >> 32));
            acc.x = fmaf(w, v[u].x, acc.x);
            acc.y = fmaf(w, v[u].y, acc.y);
            acc.z = fmaf(w, v[u].z, acc.z);
            acc.w = fmaf(w, v[u].w, acc.w);
        }
    }
    if (i + 4 <= end) {
        unsigned long long r[4];
        #pragma unroll
        for (int u = 0; u < 4; u++) r[u] = g_edge[i + u];
        float4 v[4];
        #pragma unroll
        for (int u = 0; u < 4; u++)
            v[u] = ((const float4*)(src + (size_t)(unsigned)r[u] * FDIM))[lane];
        #pragma unroll
        for (int u = 0; u < 4; u++) {
            float w = __uint_as_float((unsigned)(r[u] >> 32));
            acc.x = fmaf(w, v[u].x, acc.x);
            acc.y = fmaf(w, v[u].y, acc.y);
            acc.z = fmaf(w, v[u].z, acc.z);
            acc.w = fmaf(w, v[u].w, acc.w);
        }
        i += 4;
    }
    for (; i < end; i++) {
        unsigned long long r = g_edge[i];
        float4 v = ((const float4*)(src + (size_t)(unsigned)r * FDIM))[lane];
        float w = __uint_as_float((unsigned)(r >> 32));
        acc.x = fmaf(w, v.x, acc.x);
        acc.y = fmaf(w, v.y, acc.y);
        acc.z = fmaf(w, v.z, acc.z);
        acc.w = fmaf(w, v.w, acc.w);
    }

    float4 o;
    if (prev) {
        float4 pv = ((const float4*)(prev + (size_t)node * FDIM))[lane];
        o.x = scale * acc.x - pv.x;
        o.y = scale * acc.y - pv.y;
        o.z = scale * acc.z - pv.z;
        o.w = scale * acc.w - pv.w;
    } else {
        o.x = scale * acc.x;
        o.y = scale * acc.y;
        o.z = scale * acc.z;
        o.w = scale * acc.w;
    }
    ((float4*)(dst + (size_t)node * FDIM))[lane] = o;
}

// ---------------- 5. fused: out = InstanceNorm(sum_k T_k @ W_k + b), ReLU ----
// v2: no smem T staging — T rows read as uniform LDG.128 (all lanes same addr,
// L1-resident after first touch). smem = W (96 KB) + bias -> 2 blocks/SM.
#define FK_WARPS 8
#define FK_NPW   8
#define FK_NPB   (FK_WARPS * FK_NPW)

__global__ void __launch_bounds__(256, 2)
k_final(const float* __restrict__ x, const float* __restrict__ W,
        const float* __restrict__ b, float* __restrict__ out) {
    extern __shared__ float sm[];
    float* sW = sm;                       // 6*64*64 floats = 96 KB
    float* sb = sm + KCHEB * FDIM * FDIM; // 64 floats

    int tid = threadIdx.x;
    for (int i = tid; i < KCHEB * FDIM * FDIM / 4; i += blockDim.x)
        ((float4*)sW)[i] = ((const float4*)W)[i];
    if (tid < FDIM) sb[tid] = b[tid];
    __syncthreads();

    int warp = tid >> 5, lane = tid & 31;
    int nbase = blockIdx.x * FK_NPB + warp * FK_NPW;

    unsigned long long acc[FK_NPW];
    unsigned long long bias_u = *(const unsigned long long*)(sb + 2 * lane);
    #pragma unroll
    for (int j = 0; j < FK_NPW; j++) acc[j] = bias_u;

    #pragma unroll
    for (int k = 0; k < KCHEB; k++) {
        const float* Tsrc = (k == 0) ? x : g_T[k - 1];
        const float* rowp[FK_NPW];
        #pragma unroll
        for (int j = 0; j < FK_NPW; j++) {
            int n = nbase + j;
            rowp[j] = Tsrc + (size_t)(n < NNODES ? n : 0) * FDIM;
        }
        #pragma unroll 4
        for (int i0 = 0; i0 < FDIM; i0 += 4) {
            unsigned long long wv[4];
            #pragma unroll
            for (int u = 0; u < 4; u++)
                wv[u] = *(const unsigned long long*)(sW + ((k * FDIM + i0 + u) * FDIM) + 2 * lane);
            #pragma unroll
            for (int j = 0; j < FK_NPW; j++) {
                float4 t = *(const float4*)(rowp[j] + i0);   // uniform LDG.128
                fma2(acc[j], t.x, wv[0]);
                fma2(acc[j], t.y, wv[1]);
                fma2(acc[j], t.z, wv[2]);
                fma2(acc[j], t.w, wv[3]);
            }
        }
    }

    #pragma unroll
    for (int j = 0; j < FK_NPW; j++) {
        float2 y = unpack2(acc[j]);
        float s = y.x + y.y;
        float q = y.x * y.x + y.y * y.y;
        #pragma unroll
        for (int off = 16; off > 0; off >>= 1) {
            s += __shfl_xor_sync(0xffffffffu, s, off);
            q += __shfl_xor_sync(0xffffffffu, q, off);
        }
        float mean = s * (1.0f / FDIM);
        float var  = q * (1.0f / FDIM) - mean * mean;
        float rstd = rsqrtf(var + 1e-5f);
        float2 r;
        r.x = fmaxf((y.x - mean) * rstd, 0.0f);
        r.y = fmaxf((y.y - mean) * rstd, 0.0f);
        int n = nbase + j;
        if (n < NNODES)
            ((float2*)(out + (size_t)n * FDIM))[lane] = r;
    }
}

// ---------------- launch ------------------------------------------------------
extern "C" void kernel_launch(void* const* d_in, const int* in_sizes, int n_in,
                              void* d_out, int out_size) {
    const float* x  = (const float*)d_in[0];
    const int*   ei = (const int*)d_in[1];     // int32 edge_index
    const float* W  = (const float*)d_in[2];
    const float* b  = (const float*)d_in[3];
    float*       out = (float*)d_out;

    void* p_degi; cudaGetSymbolAddress(&p_degi, g_degi);
    void* p_T;    cudaGetSymbolAddress(&p_T, g_T);
    float* T = (float*)p_T;

    const int TB = 256;
    cudaMemsetAsync(p_degi, 0, NNODES * sizeof(int));
    k_count<<<(NEDGES + TB - 1) / TB, TB>>>(ei);
    k_scan <<<1, 1024>>>();
    k_fill <<<(NEDGES + TB - 1) / TB, TB>>>(ei);

    const int GG = (NNODES * 16 + TB - 1) / TB;
    float* T1 = T;
    float* T2 = T + (size_t)1 * NF;
    float* T3 = T + (size_t)2 * NF;
    float* T4 = T + (size_t)3 * NF;
    float* T5 = T + (size_t)4 * NF;

    k_gather<<<GG, TB>>>(x,  nullptr, T1, 1.0f);
    k_gather<<<GG, TB>>>(T1, x,       T2, 2.0f);
    k_gather<<<GG, TB>>>(T2, T1,      T3, 2.0f);
    k_gather<<<GG, TB>>>(T3, T2,      T4, 2.0f);
    k_gather<<<GG, TB>>>(T4, T3,      T5, 2.0f);

    int smem = (KCHEB * FDIM * FDIM + FDIM) * (int)sizeof(float);
    cudaFuncSetAttribute(k_final, cudaFuncAttributeMaxDynamicSharedMemorySize, smem);
    k_final<<<(NNODES + FK_NPB - 1) / FK_NPB, 256, smem>>>(x, W, b, out);
}

// round 10
// speedup vs baseline: 1.0694x; 1.0694x over previous
#include <cuda_runtime.h>
#include <cstdint>

#define NNODES 100000
#define NEDGES 1600000
#define FDIM   64
#define KCHEB  6
#define NF     (NNODES * FDIM)

// ---------------- scratch (device globals) ----------------------------------
__device__ int   g_degi[NNODES];
__device__ float g_dis[NNODES];
__device__ int   g_rowptr[NNODES + 1];
__device__ int   g_cursor[NNODES];
__device__ unsigned long long g_edge[NEDGES];   // packed (w<<32 | col*256)
__device__ float g_T[5][NF];                    // T1..T5 (T0 = x input)

// ---------------- helpers ----------------------------------------------------
__device__ __forceinline__ float2 unpack2(unsigned long long u) {
    float2 v;
    asm("mov.b64 {%0, %1}, %2;" : "=f"(v.x), "=f"(v.y) : "l"(u));
    return v;
}
__device__ __forceinline__ void fma2(unsigned long long &acc, float t, unsigned long long w) {
    unsigned long long tt;
    asm("mov.b64 %0, {%1, %1};" : "=l"(tt) : "f"(t));
    asm("fma.rn.f32x2 %0, %1, %2, %0;" : "+l"(acc) : "l"(tt), "l"(w));
}

// ---------------- 1. degree count (int) --------------------------------------
__global__ void k_count(const int* __restrict__ ei) {
    int e = blockIdx.x * blockDim.x + threadIdx.x;
    if (e >= NEDGES) return;
    atomicAdd(&g_degi[ei[e]], 1);
}

// ---------------- 2. scan -> rowptr, plus D^{-1/2} (fused) --------------------
__global__ void __launch_bounds__(1024, 1) k_scan() {
    __shared__ int warpsum[32];
    int t = threadIdx.x;
    const int CH = (NNODES + 1023) / 1024;
    int base = t * CH;
    int sum = 0;
    for (int j = 0; j < CH; j++) {
        int i = base + j;
        if (i < NNODES) sum += g_degi[i];
    }
    int lane = t & 31, w = t >> 5;
    int v = sum;
    #pragma unroll
    for (int off = 1; off < 32; off <<= 1) {
        int u = __shfl_up_sync(0xffffffffu, v, off);
        if (lane >= off) v += u;
    }
    if (lane == 31) warpsum[w] = v;
    __syncthreads();
    if (w == 0) {
        int s = warpsum[lane];
        #pragma unroll
        for (int off = 1; off < 32; off <<= 1) {
            int u = __shfl_up_sync(0xffffffffu, s, off);
            if (lane >= off) s += u;
        }
        warpsum[lane] = s;
    }
    __syncthreads();
    int off = (v - sum) + (w ? warpsum[w - 1] : 0);   // exclusive prefix
    for (int j = 0; j < CH; j++) {
        int i = base + j;
        if (i < NNODES) {
            int d = g_degi[i];
            g_rowptr[i] = off;
            g_cursor[i] = 0;
            g_dis[i] = (d > 0) ? rsqrtf((float)d) : 0.0f;
            off += d;
        }
    }
    if (t == 1023) g_rowptr[NNODES] = NEDGES;
}

// ---------------- 3. fill CSR records (col byte-offset, w) --------------------
__global__ void k_fill(const int* __restrict__ ei) {
    int e = blockIdx.x * blockDim.x + threadIdx.x;
    if (e >= NEDGES) return;
    int r = ei[e];
    int c = ei[NEDGES + e];
    float w = -g_dis[r] * g_dis[c];
    int pos = atomicAdd(&g_cursor[r], 1);
    unsigned long long rec = ((unsigned long long)__float_as_uint(w) << 32)
                           | (unsigned)(c << 8);           // pre-scaled byte offset
    g_edge[g_rowptr[r] + pos] = rec;
}

// ---------------- 4. gather prop: dst[n] = scale*sum_e w*src[col] - prev[n] ---
// 16 lanes per node (float4 per lane), 2 nodes per warp, 8-deep batch.
// Record low word is the row byte-offset -> one 32-bit add per address.
__global__ void __launch_bounds__(256)
k_gather(const float* __restrict__ src, const float* __restrict__ prev,
         float* __restrict__ dst, float scale) {
    int gid = blockIdx.x * blockDim.x + threadIdx.x;
    int node = gid >> 4;
    if (node >= NNODES) return;
    int lane = gid & 15;
    const char* sb = (const char*)src + lane * 16;
    int i = g_rowptr[node], end = g_rowptr[node + 1];
    float4 acc = make_float4(0.0f, 0.0f, 0.0f, 0.0f);

    for (; i + 8 <= end; i += 8) {
        unsigned long long r[8];
        #pragma unroll
        for (int u = 0; u < 8; u++) r[u] = g_edge[i + u];
        float4 v[8];
        #pragma unroll
        for (int u = 0; u < 8; u++)
            v[u] = *(const float4*)(sb + (unsigned)r[u]);
        #pragma unroll
        for (int u = 0; u < 8; u++) {
            float w = __uint_as_float((unsigned)(r[u] >> 32));
            acc.x = fmaf(w, v[u].x, acc.x);
            acc.y = fmaf(w, v[u].y, acc.y);
            acc.z = fmaf(w, v[u].z, acc.z);
            acc.w = fmaf(w, v[u].w, acc.w);
        }
    }
    if (i + 4 <= end) {
        unsigned long long r[4];
        #pragma unroll
        for (int u = 0; u < 4; u++) r[u] = g_edge[i + u];
        float4 v[4];
        #pragma unroll
        for (int u = 0; u < 4; u++)
            v[u] = *(const float4*)(sb + (unsigned)r[u]);
        #pragma unroll
        for (int u = 0; u < 4; u++) {
            float w = __uint_as_float((unsigned)(r[u] >> 32));
            acc.x = fmaf(w, v[u].x, acc.x);
            acc.y = fmaf(w, v[u].y, acc.y);
            acc.z = fmaf(w, v[u].z, acc.z);
            acc.w = fmaf(w, v[u].w, acc.w);
        }
        i += 4;
    }
    for (; i < end; i++) {
        unsigned long long r = g_edge[i];
        float4 v = *(const float4*)(sb + (unsigned)r);
        float w = __uint_as_float((unsigned)(r >> 32));
        acc.x = fmaf(w, v.x, acc.x);
        acc.y = fmaf(w, v.y, acc.y);
        acc.z = fmaf(w, v.z, acc.z);
        acc.w = fmaf(w, v.w, acc.w);
    }

    float4 o;
    if (prev) {
        float4 pv = ((const float4*)(prev + (size_t)node * FDIM))[lane];
        o.x = scale * acc.x - pv.x;
        o.y = scale * acc.y - pv.y;
        o.z = scale * acc.z - pv.z;
        o.w = scale * acc.w - pv.w;
    } else {
        o.x = scale * acc.x;
        o.y = scale * acc.y;
        o.z = scale * acc.z;
        o.w = scale * acc.w;
    }
    ((float4*)(dst + (size_t)node * FDIM))[lane] = o;
}

// ---------------- 5. fused: out = InstanceNorm(sum_k T_k @ W_k + b), ReLU ----
// v1 (proven): per-warp smem staging of T rows + smem W, fp32x2 FMA.
#define FK_WARPS 8
#define FK_NPW   8
#define FK_NPB   (FK_WARPS * FK_NPW)

__global__ void __launch_bounds__(256, 1)
k_final(const float* __restrict__ x, const float* __restrict__ W,
        const float* __restrict__ b, float* __restrict__ out) {
    extern __shared__ float sm[];
    float* sW = sm;
    float* sT = sm + KCHEB * FDIM * FDIM;
    float* sb = sT + FK_WARPS * KCHEB * FK_NPW * FDIM;

    int tid = threadIdx.x;
    for (int i = tid; i < KCHEB * FDIM * FDIM / 4; i += blockDim.x)
        ((float4*)sW)[i] = ((const float4*)W)[i];
    if (tid < FDIM) sb[tid] = b[tid];
    __syncthreads();

    int warp = tid >> 5, lane = tid & 31;
    int nbase = blockIdx.x * FK_NPB + warp * FK_NPW;
    float* sTw = sT + warp * (KCHEB * FK_NPW * FDIM);

    #pragma unroll
    for (int k = 0; k < KCHEB; k++) {
        const float* Tsrc = (k == 0) ? x : g_T[k - 1];
        #pragma unroll
        for (int j = 0; j < FK_NPW; j++) {
            int n = nbase + j;
            if (n < NNODES) {
                float2 v = ((const float2*)(Tsrc + (size_t)n * FDIM))[lane];
                ((float2*)(sTw + (k * FK_NPW + j) * FDIM))[lane] = v;
            }
        }
    }
    __syncwarp();

    unsigned long long acc[FK_NPW];
    unsigned long long bias_u = *(const unsigned long long*)(sb + 2 * lane);
    #pragma unroll
    for (int j = 0; j < FK_NPW; j++) acc[j] = bias_u;

    #pragma unroll
    for (int k = 0; k < KCHEB; k++) {
        #pragma unroll 4
        for (int i0 = 0; i0 < FDIM; i0 += 4) {
            unsigned long long wv[4];
            #pragma unroll
            for (int u = 0; u < 4; u++)
                wv[u] = *(const unsigned long long*)(sW + ((k * FDIM + i0 + u) * FDIM) + 2 * lane);
            #pragma unroll
            for (int j = 0; j < FK_NPW; j++) {
                float4 t = *(const float4*)(sTw + (k * FK_NPW + j) * FDIM + i0);
                fma2(acc[j], t.x, wv[0]);
                fma2(acc[j], t.y, wv[1]);
                fma2(acc[j], t.z, wv[2]);
                fma2(acc[j], t.w, wv[3]);
            }
        }
    }

    #pragma unroll
    for (int j = 0; j < FK_NPW; j++) {
        float2 y = unpack2(acc[j]);
        float s = y.x + y.y;
        float q = y.x * y.x + y.y * y.y;
        #pragma unroll
        for (int off = 16; off > 0; off >>= 1) {
            s += __shfl_xor_sync(0xffffffffu, s, off);
            q += __shfl_xor_sync(0xffffffffu, q, off);
        }
        float mean = s * (1.0f / FDIM);
        float var  = q * (1.0f / FDIM) - mean * mean;
        float rstd = rsqrtf(var + 1e-5f);
        float2 r;
        r.x = fmaxf((y.x - mean) * rstd, 0.0f);
        r.y = fmaxf((y.y - mean) * rstd, 0.0f);
        int n = nbase + j;
        if (n < NNODES)
            ((float2*)(out + (size_t)n * FDIM))[lane] = r;
    }
}

// ---------------- launch ------------------------------------------------------
extern "C" void kernel_launch(void* const* d_in, const int* in_sizes, int n_in,
                              void* d_out, int out_size) {
    const float* x  = (const float*)d_in[0];
    const int*   ei = (const int*)d_in[1];     // int32 edge_index
    const float* W  = (const float*)d_in[2];
    const float* b  = (const float*)d_in[3];
    float*       out = (float*)d_out;

    void* p_degi; cudaGetSymbolAddress(&p_degi, g_degi);
    void* p_T;    cudaGetSymbolAddress(&p_T, g_T);
    float* T = (float*)p_T;

    const int TB = 256;
    cudaMemsetAsync(p_degi, 0, NNODES * sizeof(int));
    k_count<<<(NEDGES + TB - 1) / TB, TB>>>(ei);
    k_scan <<<1, 1024>>>();
    k_fill <<<(NEDGES + TB - 1) / TB, TB>>>(ei);

    const int GG = (NNODES * 16 + TB - 1) / TB;
    float* T1 = T;
    float* T2 = T + (size_t)1 * NF;
    float* T3 = T + (size_t)2 * NF;
    float* T4 = T + (size_t)3 * NF;
    float* T5 = T + (size_t)4 * NF;

    k_gather<<<GG, TB>>>(x,  nullptr, T1, 1.0f);
    k_gather<<<GG, TB>>>(T1, x,       T2, 2.0f);
    k_gather<<<GG, TB>>>(T2, T1,      T3, 2.0f);
    k_gather<<<GG, TB>>>(T3, T2,      T4, 2.0f);
    k_gather<<<GG, TB>>>(T4, T3,      T5, 2.0f);

    int smem = (KCHEB * FDIM * FDIM + FK_WARPS * KCHEB * FK_NPW * FDIM + FDIM) * (int)sizeof(float);
    cudaFuncSetAttribute(k_final, cudaFuncAttributeMaxDynamicSharedMemorySize, smem);
    k_final<<<(NNODES + FK_NPB - 1) / FK_NPB, 256, smem>>>(x, W, b, out);
}

// round 13
// speedup vs baseline: 1.2053x; 1.1271x over previous
#include <cuda_runtime.h>
#include <cstdint>

#define NNODES 100000
#define NEDGES 1600000
#define FDIM   64
#define KCHEB  6
#define NF     (NNODES * FDIM)

// ---------------- scratch (device globals) ----------------------------------
__device__ int   g_degi[NNODES];
__device__ float g_dis[NNODES];
__device__ int   g_rowptr[NNODES + 1];
__device__ int   g_cursor[NNODES];
__device__ unsigned long long g_edge[NEDGES];   // packed (w<<32 | col*256)
__device__ float g_T[5][NF];                    // T1..T5 (T0 = x input)

// ---------------- helpers ----------------------------------------------------
__device__ __forceinline__ float2 unpack2(unsigned long long u) {
    float2 v;
    asm("mov.b64 {%0, %1}, %2;" : "=f"(v.x), "=f"(v.y) : "l"(u));
    return v;
}
__device__ __forceinline__ void fma2(unsigned long long &acc, float t, unsigned long long w) {
    unsigned long long tt;
    asm("mov.b64 %0, {%1, %1};" : "=l"(tt) : "f"(t));
    asm("fma.rn.f32x2 %0, %1, %2, %0;" : "+l"(acc) : "l"(tt), "l"(w));
}

// ---------------- 1. degree count (int) --------------------------------------
__global__ void k_count(const int* __restrict__ ei) {
    int e = blockIdx.x * blockDim.x + threadIdx.x;
    if (e >= NEDGES) return;
    atomicAdd(&g_degi[ei[e]], 1);
}

// ---------------- 2. D^{-1/2} (grid-wide) -------------------------------------
__global__ void k_dis() {
    int i = blockIdx.x * blockDim.x + threadIdx.x;
    if (i >= NNODES) return;
    int d = g_degi[i];
    g_dis[i] = (d > 0) ? rsqrtf((float)d) : 0.0f;
}

// ---------------- 3. single-block chunked exclusive scan -> rowptr ------------
__global__ void __launch_bounds__(1024, 1) k_scan() {
    __shared__ int warpsum[32];
    int t = threadIdx.x;
    const int CH = (NNODES + 1023) / 1024;
    int base = t * CH;
    int sum = 0;
    for (int j = 0; j < CH; j++) {
        int i = base + j;
        if (i < NNODES) sum += g_degi[i];
    }
    int lane = t & 31, w = t >> 5;
    int v = sum;
    #pragma unroll
    for (int off = 1; off < 32; off <<= 1) {
        int u = __shfl_up_sync(0xffffffffu, v, off);
        if (lane >= off) v += u;
    }
    if (lane == 31) warpsum[w] = v;
    __syncthreads();
    if (w == 0) {
        int s = warpsum[lane];
        #pragma unroll
        for (int off = 1; off < 32; off <<= 1) {
            int u = __shfl_up_sync(0xffffffffu, s, off);
            if (lane >= off) s += u;
        }
        warpsum[lane] = s;
    }
    __syncthreads();
    int off = (v - sum) + (w ? warpsum[w - 1] : 0);   // exclusive prefix
    for (int j = 0; j < CH; j++) {
        int i = base + j;
        if (i < NNODES) {
            g_rowptr[i] = off;
            g_cursor[i] = 0;
            off += g_degi[i];
        }
    }
    if (t == 1023) g_rowptr[NNODES] = NEDGES;
}

// ---------------- 4. fill CSR records (col byte-offset, w) --------------------
__global__ void k_fill(const int* __restrict__ ei) {
    int e = blockIdx.x * blockDim.x + threadIdx.x;
    if (e >= NEDGES) return;
    int r = ei[e];
    int c = ei[NEDGES + e];
    float w = -g_dis[r] * g_dis[c];
    int pos = atomicAdd(&g_cursor[r], 1);
    unsigned long long rec = ((unsigned long long)__float_as_uint(w) << 32)
                           | (unsigned)(c << 8);           // pre-scaled byte offset
    g_edge[g_rowptr[r] + pos] = rec;
}

// ---------------- 5. gather prop: dst[n] = scale*sum_e w*src[col] - prev[n] ---
// 16 lanes per node (float4 per lane), 2 nodes per warp, 8-deep batch.
__global__ void __launch_bounds__(256)
k_gather(const float* __restrict__ src, const float* __restrict__ prev,
         float* __restrict__ dst, float scale) {
    int gid = blockIdx.x * blockDim.x + threadIdx.x;
    int node = gid >> 4;
    if (node >= NNODES) return;
    int lane = gid & 15;
    const char* sb = (const char*)src + lane * 16;
    int i = g_rowptr[node], end = g_rowptr[node + 1];
    float4 acc = make_float4(0.0f, 0.0f, 0.0f, 0.0f);

    for (; i + 8 <= end; i += 8) {
        unsigned long long r[8];
        #pragma unroll
        for (int u = 0; u < 8; u++) r[u] = g_edge[i + u];
        float4 v[8];
        #pragma unroll
        for (int u = 0; u < 8; u++)
            v[u] = *(const float4*)(sb + (unsigned)r[u]);
        #pragma unroll
        for (int u = 0; u < 8; u++) {
            float w = __uint_as_float((unsigned)(r[u] >> 32));
            acc.x = fmaf(w, v[u].x, acc.x);
            acc.y = fmaf(w, v[u].y, acc.y);
            acc.z = fmaf(w, v[u].z, acc.z);
            acc.w = fmaf(w, v[u].w, acc.w);
        }
    }
    if (i + 4 <= end) {
        unsigned long long r[4];
        #pragma unroll
        for (int u = 0; u < 4; u++) r[u] = g_edge[i + u];
        float4 v[4];
        #pragma unroll
        for (int u = 0; u < 4; u++)
            v[u] = *(const float4*)(sb + (unsigned)r[u]);
        #pragma unroll
        for (int u = 0; u < 4; u++) {
            float w = __uint_as_float((unsigned)(r[u] >> 32));
            acc.x = fmaf(w, v[u].x, acc.x);
            acc.y = fmaf(w, v[u].y, acc.y);
            acc.z = fmaf(w, v[u].z, acc.z);
            acc.w = fmaf(w, v[u].w, acc.w);
        }
        i += 4;
    }
    for (; i < end; i++) {
        unsigned long long r = g_edge[i];
        float4 v = *(const float4*)(sb + (unsigned)r);
        float w = __uint_as_float((unsigned)(r >> 32));
        acc.x = fmaf(w, v.x, acc.x);
        acc.y = fmaf(w, v.y, acc.y);
        acc.z = fmaf(w, v.z, acc.z);
        acc.w = fmaf(w, v.w, acc.w);
    }

    float4 o;
    if (prev) {
        float4 pv = ((const float4*)(prev + (size_t)node * FDIM))[lane];
        o.x = scale * acc.x - pv.x;
        o.y = scale * acc.y - pv.y;
        o.z = scale * acc.z - pv.z;
        o.w = scale * acc.w - pv.w;
    } else {
        o.x = scale * acc.x;
        o.y = scale * acc.y;
        o.z = scale * acc.z;
        o.w = scale * acc.w;
    }
    ((float4*)(dst + (size_t)node * FDIM))[lane] = o;
}

// ---------------- 6. fused: out = InstanceNorm(sum_k T_k @ W_k + b), ReLU ----
// v4: 512-thread block (16 warps), single shared W copy, per-k T staging.
// smem = 96 KB (W) + 16 warps * 2 KB (T) + 256 B (bias) = 128.3 KB, 1 block/SM.
#define FK_WARPS 16
#define FK_NPW   8
#define FK_NPB   (FK_WARPS * FK_NPW)     // 128 nodes per block
#define FK_THREADS (FK_WARPS * 32)       // 512

__global__ void __launch_bounds__(FK_THREADS, 1)
k_final(const float* __restrict__ x, const float* __restrict__ W,
        const float* __restrict__ b, float* __restrict__ out) {
    extern __shared__ float sm[];
    float* sW = sm;                                   // 6*64*64 = 24576 floats
    float* sT = sm + KCHEB * FDIM * FDIM;             // 16 warps * 8*64 = 8192
    float* sb = sT + FK_WARPS * FK_NPW * FDIM;        // 64 floats

    int tid = threadIdx.x;
    for (int i = tid; i < KCHEB * FDIM * FDIM / 4; i += FK_THREADS)
        ((float4*)sW)[i] = ((const float4*)W)[i];
    if (tid < FDIM) sb[tid] = b[tid];
    __syncthreads();

    int warp = tid >> 5, lane = tid & 31;
    int nbase = blockIdx.x * FK_NPB + warp * FK_NPW;
    float* sTw = sT + warp * (FK_NPW * FDIM);

    unsigned long long acc[FK_NPW];
    unsigned long long bias_u = *(const unsigned long long*)(sb + 2 * lane);
    #pragma unroll
    for (int j = 0; j < FK_NPW; j++) acc[j] = bias_u;

    #pragma unroll
    for (int k = 0; k < KCHEB; k++) {
        const float* Tsrc = (k == 0) ? x : g_T[k - 1];
        // stage this term's 8 rows for the warp (float2 per lane)
        #pragma unroll
        for (int j = 0; j < FK_NPW; j++) {
            int n = nbase + j;
            if (n < NNODES) {
                float2 v = ((const float2*)(Tsrc + (size_t)n * FDIM))[lane];
                ((float2*)(sTw + j * FDIM))[lane] = v;
            }
        }
        __syncwarp();

        #pragma unroll 4
        for (int i0 = 0; i0 < FDIM; i0 += 4) {
            unsigned long long wv[4];
            #pragma unroll
            for (int u = 0; u < 4; u++)
                wv[u] = *(const unsigned long long*)(sW + ((k * FDIM + i0 + u) * FDIM) + 2 * lane);
            #pragma unroll
            for (int j = 0; j < FK_NPW; j++) {
                float4 t = *(const float4*)(sTw + j * FDIM + i0);
                fma2(acc[j], t.x, wv[0]);
                fma2(acc[j], t.y, wv[1]);
                fma2(acc[j], t.z, wv[2]);
                fma2(acc[j], t.w, wv[3]);
            }
        }
        __syncwarp();   // before next k's staging overwrites sTw
    }

    #pragma unroll
    for (int j = 0; j < FK_NPW; j++) {
        float2 y = unpack2(acc[j]);
        float s = y.x + y.y;
        float q = y.x * y.x + y.y * y.y;
        #pragma unroll
        for (int off = 16; off > 0; off >>= 1) {
            s += __shfl_xor_sync(0xffffffffu, s, off);
            q += __shfl_xor_sync(0xffffffffu, q, off);
        }
        float mean = s * (1.0f / FDIM);
        float var  = q * (1.0f / FDIM) - mean * mean;
        float rstd = rsqrtf(var + 1e-5f);
        float2 r;
        r.x = fmaxf((y.x - mean) * rstd, 0.0f);
        r.y = fmaxf((y.y - mean) * rstd, 0.0f);
        int n = nbase + j;
        if (n < NNODES)
            ((float2*)(out + (size_t)n * FDIM))[lane] = r;
    }
}

// ---------------- launch ------------------------------------------------------
extern "C" void kernel_launch(void* const* d_in, const int* in_sizes, int n_in,
                              void* d_out, int out_size) {
    const float* x  = (const float*)d_in[0];
    const int*   ei = (const int*)d_in[1];     // int32 edge_index
    const float* W  = (const float*)d_in[2];
    const float* b  = (const float*)d_in[3];
    float*       out = (float*)d_out;

    void* p_degi; cudaGetSymbolAddress(&p_degi, g_degi);
    void* p_T;    cudaGetSymbolAddress(&p_T, g_T);
    float* T = (float*)p_T;

    const int TB = 256;
    cudaMemsetAsync(p_degi, 0, NNODES * sizeof(int));
    k_count<<<(NEDGES + TB - 1) / TB, TB>>>(ei);
    k_dis  <<<(NNODES + TB - 1) / TB, TB>>>();
    k_scan <<<1, 1024>>>();
    k_fill <<<(NEDGES + TB - 1) / TB, TB>>>(ei);

    const int GG = (NNODES * 16 + TB - 1) / TB;
    float* T1 = T;
    float* T2 = T + (size_t)1 * NF;
    float* T3 = T + (size_t)2 * NF;
    float* T4 = T + (size_t)3 * NF;
    float* T5 = T + (size_t)4 * NF;

    k_gather<<<GG, TB>>>(x,  nullptr, T1, 1.0f);
    k_gather<<<GG, TB>>>(T1, x,       T2, 2.0f);
    k_gather<<<GG, TB>>>(T2, T1,      T3, 2.0f);
    k_gather<<<GG, TB>>>(T3, T2,      T4, 2.0f);
    k_gather<<<GG, TB>>>(T4, T3,      T5, 2.0f);

    int smem = (KCHEB * FDIM * FDIM + FK_WARPS * FK_NPW * FDIM + FDIM) * (int)sizeof(float);
    cudaFuncSetAttribute(k_final, cudaFuncAttributeMaxDynamicSharedMemorySize, smem);
    k_final<<<(NNODES + FK_NPB - 1) / FK_NPB, FK_THREADS, smem>>>(x, W, b, out);
}